// round 3
// baseline (speedup 1.0000x reference)
#include <cuda_runtime.h>
#include <math.h>

#define MODEL_DIM 2048
#define PROJ_DIM  256
#define NEXP      64
#define NEG_INF   (-1e9f)
#define CLAMP_MAX 4.605170185988091f   /* log(100) */
#define MAX_TOK   16384

// Scratch (static device arrays: allocation-free per harness rules)
__device__ float h_g[(size_t)MAX_TOK * PROJ_DIM];   // 16 MB: h = x W^T + b
__device__ float simn_g[PROJ_DIM * NEXP];           // column-normalized sim matrix
__device__ float scale_g;                           // exp(min(temp, log 100))
__device__ float activecnt_g;                       // sum(experts_mask)

// ---------------------------------------------------------------------------
// Prep: normalize sim columns, compute scale + active count
// ---------------------------------------------------------------------------
__global__ void prep_kernel(const float* __restrict__ sim,
                            const float* __restrict__ temp,
                            const float* __restrict__ mask) {
    __shared__ float cnorm[NEXP];
    int t = threadIdx.x;
    if (t < NEXP) {
        float ss = 0.f;
        for (int p = 0; p < PROJ_DIM; p++) {
            float v = sim[p * NEXP + t];
            ss += v * v;
        }
        cnorm[t] = fmaxf(sqrtf(ss), 1e-12f);
    }
    if (t == 0) {
        float tt = temp[0];
        if (tt > CLAMP_MAX) tt = CLAMP_MAX;
        scale_g = expf(tt);
        float a = 0.f;
        for (int e = 0; e < NEXP; e++) a += mask[e];
        activecnt_g = a;
    }
    __syncthreads();
    for (int i = t; i < PROJ_DIM * NEXP; i += blockDim.x)
        simn_g[i] = sim[i] / cnorm[i & (NEXP - 1)];
}

// ---------------------------------------------------------------------------
// SGEMM: h[M,256] = x[M,2048] * W[256,2048]^T + b
// BM=128, BN=128, BK=16, 256 threads, 8x8 per thread, double-buffered SMEM
// ---------------------------------------------------------------------------
#define BM 128
#define BN 128
#define BK 16

__global__ void __launch_bounds__(256) gemm_kernel(const float* __restrict__ x,
                                                   const float* __restrict__ W,
                                                   const float* __restrict__ b) {
    __shared__ float As[2][BK][BM];
    __shared__ float Bs[2][BK][BN];

    const int tid = threadIdx.x;
    const int bm = blockIdx.x * BM;
    const int bn = blockIdx.y * BN;
    const int tr = tid >> 4;        // 0..15
    const int tc = tid & 15;        // 0..15

    // Global-load mapping: 128 rows x 16 k per tile; each thread loads 2 float4
    const int lr = tid >> 2;            // 0..63
    const int lk = (tid & 3) * 4;       // 0,4,8,12
    const float* xA = x + (size_t)(bm + lr) * MODEL_DIM + lk;
    const float* wB = W + (size_t)(bn + lr) * MODEL_DIM + lk;

    float4 ra0, ra1, rb0, rb1;
    ra0 = *(const float4*)(xA);
    ra1 = *(const float4*)(xA + (size_t)64 * MODEL_DIM);
    rb0 = *(const float4*)(wB);
    rb1 = *(const float4*)(wB + (size_t)64 * MODEL_DIM);

    As[0][lk + 0][lr] = ra0.x; As[0][lk + 1][lr] = ra0.y;
    As[0][lk + 2][lr] = ra0.z; As[0][lk + 3][lr] = ra0.w;
    As[0][lk + 0][lr + 64] = ra1.x; As[0][lk + 1][lr + 64] = ra1.y;
    As[0][lk + 2][lr + 64] = ra1.z; As[0][lk + 3][lr + 64] = ra1.w;
    Bs[0][lk + 0][lr] = rb0.x; Bs[0][lk + 1][lr] = rb0.y;
    Bs[0][lk + 2][lr] = rb0.z; Bs[0][lk + 3][lr] = rb0.w;
    Bs[0][lk + 0][lr + 64] = rb1.x; Bs[0][lk + 1][lr + 64] = rb1.y;
    Bs[0][lk + 2][lr + 64] = rb1.z; Bs[0][lk + 3][lr + 64] = rb1.w;
    __syncthreads();

    float acc[8][8];
#pragma unroll
    for (int i = 0; i < 8; i++)
#pragma unroll
        for (int j = 0; j < 8; j++) acc[i][j] = 0.f;

    const int NT = MODEL_DIM / BK;   // 128
    for (int t = 0; t < NT; t++) {
        const int buf = t & 1;
        if (t + 1 < NT) {
            const float* pa = xA + (size_t)(t + 1) * BK;
            const float* pb = wB + (size_t)(t + 1) * BK;
            ra0 = *(const float4*)(pa);
            ra1 = *(const float4*)(pa + (size_t)64 * MODEL_DIM);
            rb0 = *(const float4*)(pb);
            rb1 = *(const float4*)(pb + (size_t)64 * MODEL_DIM);
        }
#pragma unroll
        for (int k = 0; k < BK; k++) {
            float a[8], bb8[8];
            *(float4*)(a)     = *(const float4*)&As[buf][k][tr * 8];
            *(float4*)(a + 4) = *(const float4*)&As[buf][k][tr * 8 + 4];
            *(float4*)(bb8)     = *(const float4*)&Bs[buf][k][tc * 8];
            *(float4*)(bb8 + 4) = *(const float4*)&Bs[buf][k][tc * 8 + 4];
#pragma unroll
            for (int i = 0; i < 8; i++)
#pragma unroll
                for (int j = 0; j < 8; j++)
                    acc[i][j] += a[i] * bb8[j];
        }
        if (t + 1 < NT) {
            const int nb = (t + 1) & 1;
            As[nb][lk + 0][lr] = ra0.x; As[nb][lk + 1][lr] = ra0.y;
            As[nb][lk + 2][lr] = ra0.z; As[nb][lk + 3][lr] = ra0.w;
            As[nb][lk + 0][lr + 64] = ra1.x; As[nb][lk + 1][lr + 64] = ra1.y;
            As[nb][lk + 2][lr + 64] = ra1.z; As[nb][lk + 3][lr + 64] = ra1.w;
            Bs[nb][lk + 0][lr] = rb0.x; Bs[nb][lk + 1][lr] = rb0.y;
            Bs[nb][lk + 2][lr] = rb0.z; Bs[nb][lk + 3][lr] = rb0.w;
            Bs[nb][lk + 0][lr + 64] = rb1.x; Bs[nb][lk + 1][lr + 64] = rb1.y;
            Bs[nb][lk + 2][lr + 64] = rb1.z; Bs[nb][lk + 3][lr + 64] = rb1.w;
            __syncthreads();
        }
    }

    float bv[8];
#pragma unroll
    for (int j = 0; j < 8; j++) bv[j] = b[bn + tc * 8 + j];

#pragma unroll
    for (int i = 0; i < 8; i++) {
        const int row = bm + tr * 8 + i;
        float* orow = h_g + (size_t)row * PROJ_DIM + bn + tc * 8;
        float4 v0, v1;
        v0.x = acc[i][0] + bv[0]; v0.y = acc[i][1] + bv[1];
        v0.z = acc[i][2] + bv[2]; v0.w = acc[i][3] + bv[3];
        v1.x = acc[i][4] + bv[4]; v1.y = acc[i][5] + bv[5];
        v1.z = acc[i][6] + bv[6]; v1.w = acc[i][7] + bv[7];
        *(float4*)(orow)     = v0;
        *(float4*)(orow + 4) = v1;
    }
}

// ---------------------------------------------------------------------------
// Gate: per 64-row tile: normalize rows, logits = hn @ simn, scale+mask,
// softmax, top-k via O(E^2) prefix-of-larger (== sort+cumsum+threshold)
// ---------------------------------------------------------------------------
#define HS 260                  /* padded h row stride (floats) */
#define SC 68                   /* padded score row stride */
#define GATE_SMEM ((PROJ_DIM*NEXP + 64*HS + 64*SC) * 4)

__global__ void __launch_bounds__(256) gate_kernel(const float* __restrict__ mask,
                                                   float* __restrict__ out,
                                                   int M, int out_size) {
    extern __shared__ float sm[];
    float* simn_s = sm;                       // 256*64
    float* h_s    = sm + PROJ_DIM * NEXP;     // 64*HS
    float* sc_s   = h_s + 64 * HS;            // 64*SC

    const int tid  = threadIdx.x;
    const int row0 = blockIdx.x * 64;

    // stage simn
    for (int i = tid * 4; i < PROJ_DIM * NEXP; i += 256 * 4)
        *(float4*)&simn_s[i] = *(const float4*)&simn_g[i];

    // stage 64 h rows (coalesced read, padded SMEM store)
    for (int i = tid * 4; i < 64 * PROJ_DIM; i += 256 * 4) {
        int r = i >> 8;
        int c = i & 255;
        float4 v = *(const float4*)&h_g[(size_t)(row0 + r) * PROJ_DIM + c];
        float* d = &h_s[r * HS + c];
        d[0] = v.x; d[1] = v.y; d[2] = v.z; d[3] = v.w;
    }
    __syncthreads();

    const int row = tid >> 2;    // 0..63
    const int q   = tid & 3;     // quad member: experts q*16 .. q*16+15

    // row L2 norm: each quad member sums 64 p's, reduce within quad
    float ss = 0.f;
    const float* hrow = &h_s[row * HS];
    for (int p = q * 64; p < q * 64 + 64; p++) {
        float v = hrow[p];
        ss += v * v;
    }
    ss += __shfl_xor_sync(0xffffffffu, ss, 1);
    ss += __shfl_xor_sync(0xffffffffu, ss, 2);
    const float scal = scale_g / fmaxf(sqrtf(ss), 1e-12f);

    // logits for my 16 experts
    float acc[16];
#pragma unroll
    for (int j = 0; j < 16; j++) acc[j] = 0.f;
#pragma unroll 4
    for (int p = 0; p < PROJ_DIM; p++) {
        float hv = hrow[p];
        const float* sp = &simn_s[p * NEXP + q * 16];
#pragma unroll
        for (int j = 0; j < 16; j += 4) {
            float4 s4 = *(const float4*)&sp[j];
            acc[j + 0] += hv * s4.x;
            acc[j + 1] += hv * s4.y;
            acc[j + 2] += hv * s4.z;
            acc[j + 3] += hv * s4.w;
        }
    }

    // scale + mask, write logits, compute softmax pieces
    float lg[16];
    float mymax = -3.4e38f;
#pragma unroll
    for (int j = 0; j < 16; j++) {
        int e = q * 16 + j;
        float l = acc[j] * scal;
        if (mask[e] == 0.f) l = NEG_INF;
        lg[j] = l;
        mymax = fmaxf(mymax, l);
    }
    {
        float* obase = out + (size_t)(row0 + row) * NEXP + q * 16;
#pragma unroll
        for (int j = 0; j < 16; j += 4) {
            float4 v; v.x = lg[j]; v.y = lg[j + 1]; v.z = lg[j + 2]; v.w = lg[j + 3];
            *(float4*)(obase + j) = v;
        }
    }
    mymax = fmaxf(mymax, __shfl_xor_sync(0xffffffffu, mymax, 1));
    mymax = fmaxf(mymax, __shfl_xor_sync(0xffffffffu, mymax, 2));

    float ex[16];
    float sum = 0.f;
#pragma unroll
    for (int j = 0; j < 16; j++) {
        ex[j] = expf(lg[j] - mymax);
        sum += ex[j];
    }
    sum += __shfl_xor_sync(0xffffffffu, sum, 1);
    sum += __shfl_xor_sync(0xffffffffu, sum, 2);
    const float inv = 1.f / sum;

    float scs[16];
#pragma unroll
    for (int j = 0; j < 16; j++) {
        scs[j] = ex[j] * inv + 1e-14f;
        sc_s[row * SC + q * 16 + j] = scs[j];
    }
    __syncthreads();

    // top_k: keep element iff sum of strictly-larger (w/ tie order) scores < 1
    int cnt = 0;
    const float* srow = &sc_s[row * SC];
#pragma unroll
    for (int j = 0; j < 16; j++) {
        const float v = scs[j];
        const int gi = q * 16 + j;
        float prefix = 0.f;
#pragma unroll 8
        for (int u = 0; u < NEXP; u++) {
            float su = srow[u];
            if (su > v || (su == v && u < gi)) prefix += su;
        }
        cnt += (prefix < 1.0f) ? 1 : 0;
    }
    cnt += __shfl_xor_sync(0xffffffffu, cnt, 1);
    cnt += __shfl_xor_sync(0xffffffffu, cnt, 2);

    if (q == 0 && (size_t)out_size >= (size_t)M * NEXP + (size_t)M) {
        int a = (int)activecnt_g;
        if (cnt > a) cnt = a;
        out[(size_t)M * NEXP + row0 + row] = (float)cnt;
    }
}

// ---------------------------------------------------------------------------
extern "C" void kernel_launch(void* const* d_in, const int* in_sizes, int n_in,
                              void* d_out, int out_size) {
    const float* x    = (const float*)d_in[0];
    const float* W    = (const float*)d_in[1];
    const float* b    = (const float*)d_in[2];
    const float* sim  = (const float*)d_in[3];
    const float* temp = (const float*)d_in[4];
    const float* mask = (const float*)d_in[5];
    float* out = (float*)d_out;

    const int M = in_sizes[0] / MODEL_DIM;   // 16384

    prep_kernel<<<1, 256>>>(sim, temp, mask);

    dim3 g1(M / BM, PROJ_DIM / BN);
    gemm_kernel<<<g1, 256>>>(x, W, b);

    cudaFuncSetAttribute(gate_kernel, cudaFuncAttributeMaxDynamicSharedMemorySize,
                         GATE_SMEM);
    gate_kernel<<<M / 64, 256, GATE_SMEM>>>(mask, out, M, out_size);
}

// round 6
// speedup vs baseline: 1.7910x; 1.7910x over previous
#include <cuda_runtime.h>
#include <cuda_bf16.h>
#include <math.h>
#include <stdint.h>

#define MODEL_DIM 2048
#define PROJ_DIM  256
#define NEXP      64
#define NEG_INF   (-1e9f)
#define CLAMP_MAX 4.605170185988091f   /* log(100) */
#define MAX_TOK   16384

// ---------------- static device scratch ------------------------------------
__device__ float h_g[(size_t)MAX_TOK * PROJ_DIM];      // 16 MB
__device__ __nv_bfloat16 whi_g[PROJ_DIM * MODEL_DIM];  // 1 MB
__device__ __nv_bfloat16 wlo_g[PROJ_DIM * MODEL_DIM];  // 1 MB
__device__ float simn_g[PROJ_DIM * NEXP];
__device__ float scale_g;
__device__ float activecnt_g;

// ---------------- helpers ---------------------------------------------------
__device__ __forceinline__ uint32_t smem_u32(const void* p) {
    uint32_t a;
    asm("{ .reg .u64 t; cvta.to.shared.u64 t, %1; cvt.u32.u64 %0, t; }"
        : "=r"(a) : "l"(p));
    return a;
}
__device__ __forceinline__ void cp16(uint32_t dst, const void* src) {
    asm volatile("cp.async.cg.shared.global [%0], [%1], 16;" :: "r"(dst), "l"(src));
}
#define CP_COMMIT() asm volatile("cp.async.commit_group;" ::: "memory")
#define CP_WAIT0()  asm volatile("cp.async.wait_group 0;" ::: "memory")

__device__ __forceinline__ void ldsm_x4(uint32_t* r, uint32_t addr) {
    asm volatile("ldmatrix.sync.aligned.m8n8.x4.shared.b16 {%0,%1,%2,%3}, [%4];"
                 : "=r"(r[0]), "=r"(r[1]), "=r"(r[2]), "=r"(r[3]) : "r"(addr));
}
__device__ __forceinline__ void mma_bf16(float* c, const uint32_t* a, const uint32_t* b) {
    asm volatile("mma.sync.aligned.m16n8k16.row.col.f32.bf16.bf16.f32 "
                 "{%0,%1,%2,%3}, {%4,%5,%6,%7}, {%8,%9}, {%0,%1,%2,%3};"
                 : "+f"(c[0]), "+f"(c[1]), "+f"(c[2]), "+f"(c[3])
                 : "r"(a[0]), "r"(a[1]), "r"(a[2]), "r"(a[3]), "r"(b[0]), "r"(b[1]));
}

__device__ __forceinline__ unsigned short bf16_bits(__nv_bfloat16 h) {
    return *(unsigned short*)&h;
}
// split two floats -> packed hi bf16x2 + packed lo bf16x2
__device__ __forceinline__ void split2(float a, float b, uint32_t& hi, uint32_t& lo) {
    __nv_bfloat16 ha = __float2bfloat16_rn(a), hb = __float2bfloat16_rn(b);
    float ra = a - __bfloat162float(ha), rb = b - __bfloat162float(hb);
    __nv_bfloat16 la = __float2bfloat16_rn(ra), lb = __float2bfloat16_rn(rb);
    hi = (uint32_t)bf16_bits(ha) | ((uint32_t)bf16_bits(hb) << 16);
    lo = (uint32_t)bf16_bits(la) | ((uint32_t)bf16_bits(lb) << 16);
}

// ---------------------------------------------------------------------------
// Prep: column-normalize sim, scale, active count
// ---------------------------------------------------------------------------
__global__ void prep_kernel(const float* __restrict__ sim,
                            const float* __restrict__ temp,
                            const float* __restrict__ mask) {
    __shared__ float cnorm[NEXP];
    const int tid = threadIdx.x;            // 256
    const int e = tid >> 2, part = tid & 3;
    float ss = 0.f;
    for (int p = part * 64; p < part * 64 + 64; p++) {
        float v = sim[p * NEXP + e];
        ss += v * v;
    }
    ss += __shfl_xor_sync(0xffffffffu, ss, 1);
    ss += __shfl_xor_sync(0xffffffffu, ss, 2);
    if (part == 0) cnorm[e] = fmaxf(sqrtf(ss), 1e-12f);
    if (tid == 0) {
        float tt = temp[0];
        if (tt > CLAMP_MAX) tt = CLAMP_MAX;
        scale_g = expf(tt);
        float a = 0.f;
        for (int i = 0; i < NEXP; i++) a += mask[i];
        activecnt_g = a;
    }
    __syncthreads();
    for (int i = tid; i < PROJ_DIM * NEXP; i += blockDim.x)
        simn_g[i] = sim[i] / cnorm[i & (NEXP - 1)];
}

// ---------------------------------------------------------------------------
// W fp32 -> (hi, lo) bf16
// ---------------------------------------------------------------------------
__global__ void __launch_bounds__(256) wconv_kernel(const float* __restrict__ W) {
    const size_t i = (size_t)blockIdx.x * blockDim.x + threadIdx.x;  // float4 idx
    const float4 v = ((const float4*)W)[i];
    uint32_t h0, l0, h1, l1;
    split2(v.x, v.y, h0, l0);
    split2(v.z, v.w, h1, l1);
    uint2 hh; hh.x = h0; hh.y = h1;
    uint2 ll; ll.x = l0; ll.y = l1;
    *(uint2*)&whi_g[i << 2] = hh;
    *(uint2*)&wlo_g[i << 2] = ll;
}

// ---------------------------------------------------------------------------
// Tensor-core GEMM (mma.sync bf16 split-3): h = x W^T + b
// CTA: 128x256, BK=32, 512 threads (16 warps of 32x64), double buffered
// ---------------------------------------------------------------------------
#define BM   128
#define BN   256
#define BK   32
#define NCH  (MODEL_DIM / BK)    /* 64 */
#define AST  40                  /* padded k-stride in bf16 */
#define A_HI 0
#define A_LO 10240
#define B_HI 20480
#define B_LO 40960
#define STG  61440
#define GEMM_SMEM (2 * STG)      /* 122880 */

__global__ void __launch_bounds__(512) gemm_mma_kernel(const float* __restrict__ x,
                                                       const float* __restrict__ bias) {
    extern __shared__ char smem[];
    const uint32_t sb = smem_u32(smem);
    const int tid = threadIdx.x;
    const int wid = tid >> 5, lane = tid & 31;
    const int bm = blockIdx.x * BM;

    // x staging: thread handles rows xrow and xrow+64, 4 floats at k-col xc4
    const int xrow = tid >> 3;            // 0..63
    const int xc4 = (tid & 7) * 4;        // 0..28
    const float* xp0 = x + (size_t)(bm + xrow) * MODEL_DIM + xc4;
    const float* xp1 = xp0 + (size_t)64 * MODEL_DIM;

    const int wm = (wid >> 2) * 32;       // warp m-offset
    const int wn = (wid & 3) * 64;        // warp n-offset

    float4 xr0, xr1;

#define LOAD_X(c) do { xr0 = *(const float4*)(xp0 + (c) * BK); \
                       xr1 = *(const float4*)(xp1 + (c) * BK); } while (0)

#define STORE_X(s) do {                                                        \
    char* ab = smem + (s) * STG;                                               \
    uint32_t h0, l0, h1, l1;                                                   \
    split2(xr0.x, xr0.y, h0, l0); split2(xr0.z, xr0.w, h1, l1);                \
    { uint2 hh; hh.x = h0; hh.y = h1; uint2 ll; ll.x = l0; ll.y = l1;          \
      *(uint2*)(ab + A_HI + (xrow * AST + xc4) * 2) = hh;                      \
      *(uint2*)(ab + A_LO + (xrow * AST + xc4) * 2) = ll; }                    \
    split2(xr1.x, xr1.y, h0, l0); split2(xr1.z, xr1.w, h1, l1);                \
    { uint2 hh; hh.x = h0; hh.y = h1; uint2 ll; ll.x = l0; ll.y = l1;          \
      *(uint2*)(ab + A_HI + ((xrow + 64) * AST + xc4) * 2) = hh;               \
      *(uint2*)(ab + A_LO + ((xrow + 64) * AST + xc4) * 2) = ll; }             \
} while (0)

#define CP_W(c, s) do {                                                        \
    _Pragma("unroll")                                                          \
    for (int i = 0; i < 4; i++) {                                              \
        const int id = tid + i * 512;                                          \
        const int mat = id >> 10, mid = id & 1023;                             \
        const int row = mid >> 2, u = mid & 3;                                 \
        const uint32_t dst = sb + (s) * STG + (mat ? B_LO : B_HI)              \
                             + row * (AST * 2) + u * 16;                       \
        const __nv_bfloat16* src = (mat ? wlo_g : whi_g)                       \
                             + (size_t)row * MODEL_DIM + (c) * BK + u * 8;     \
        cp16(dst, src);                                                       \
    }                                                                          \
} while (0)

    float acc[2][8][4];
#pragma unroll
    for (int i = 0; i < 2; i++)
#pragma unroll
        for (int j = 0; j < 8; j++)
#pragma unroll
            for (int k = 0; k < 4; k++) acc[i][j][k] = 0.f;

    // prologue: stage 0
    LOAD_X(0);
    CP_W(0, 0);
    STORE_X(0);
    CP_COMMIT();
    CP_WAIT0();
    __syncthreads();

    for (int c = 0; c < NCH; c++) {
        const int s = c & 1;
        if (c + 1 < NCH) {
            LOAD_X(c + 1);
            CP_W(c + 1, s ^ 1);
            CP_COMMIT();
        }

        // ---- compute on stage s ----
        const uint32_t ab = sb + s * STG;
#pragma unroll
        for (int ks = 0; ks < 2; ks++) {
            const int kk = ks * 16;
            uint32_t ah[2][4], al[2][4];
#pragma unroll
            for (int mt = 0; mt < 2; mt++) {
                const int m = wm + mt * 16 + (lane & 15);
                const int kc = kk + (lane >> 4) * 8;
                ldsm_x4(ah[mt], ab + A_HI + (m * AST + kc) * 2);
                ldsm_x4(al[mt], ab + A_LO + (m * AST + kc) * 2);
            }
            const int g = lane >> 3;
            const int brow = (g >> 1) * 8 + (lane & 7);
            const int bk = kk + (g & 1) * 8;
#pragma unroll
            for (int np = 0; np < 4; np++) {
                const int n0 = wn + np * 16;
                uint32_t bh[4], bl[4];
                ldsm_x4(bh, ab + B_HI + ((n0 + brow) * AST + bk) * 2);
                ldsm_x4(bl, ab + B_LO + ((n0 + brow) * AST + bk) * 2);
                // hh
                mma_bf16(acc[0][np * 2],     ah[0], bh);
                mma_bf16(acc[0][np * 2 + 1], ah[0], bh + 2);
                mma_bf16(acc[1][np * 2],     ah[1], bh);
                mma_bf16(acc[1][np * 2 + 1], ah[1], bh + 2);
                // hl
                mma_bf16(acc[0][np * 2],     ah[0], bl);
                mma_bf16(acc[0][np * 2 + 1], ah[0], bl + 2);
                mma_bf16(acc[1][np * 2],     ah[1], bl);
                mma_bf16(acc[1][np * 2 + 1], ah[1], bl + 2);
                // lh
                mma_bf16(acc[0][np * 2],     al[0], bh);
                mma_bf16(acc[0][np * 2 + 1], al[0], bh + 2);
                mma_bf16(acc[1][np * 2],     al[1], bh);
                mma_bf16(acc[1][np * 2 + 1], al[1], bh + 2);
            }
        }

        if (c + 1 < NCH) {
            STORE_X(s ^ 1);
            CP_WAIT0();
        }
        __syncthreads();
    }

    // ---- epilogue: add bias, write h ----
#pragma unroll
    for (int mt = 0; mt < 2; mt++) {
        const int row = bm + wm + mt * 16 + (lane >> 2);
#pragma unroll
        for (int nt = 0; nt < 8; nt++) {
            const int col = wn + nt * 8 + (lane & 3) * 2;
            const float b0 = __ldg(&bias[col]);
            const float b1 = __ldg(&bias[col + 1]);
            float2 v0, v1;
            v0.x = acc[mt][nt][0] + b0; v0.y = acc[mt][nt][1] + b1;
            v1.x = acc[mt][nt][2] + b0; v1.y = acc[mt][nt][3] + b1;
            *(float2*)&h_g[(size_t)row * PROJ_DIM + col] = v0;
            *(float2*)&h_g[(size_t)(row + 8) * PROJ_DIM + col] = v1;
        }
    }
}

// ---------------------------------------------------------------------------
// Gate (unchanged from passing R3 kernel)
// ---------------------------------------------------------------------------
#define HS 260
#define SC 68
#define GATE_SMEM ((PROJ_DIM * NEXP + 64 * HS + 64 * SC) * 4)

__global__ void __launch_bounds__(256) gate_kernel(const float* __restrict__ mask,
                                                   float* __restrict__ out,
                                                   int M, int out_size) {
    extern __shared__ float sm[];
    float* simn_s = sm;
    float* h_s = sm + PROJ_DIM * NEXP;
    float* sc_s = h_s + 64 * HS;

    const int tid = threadIdx.x;
    const int row0 = blockIdx.x * 64;

    for (int i = tid * 4; i < PROJ_DIM * NEXP; i += 256 * 4)
        *(float4*)&simn_s[i] = *(const float4*)&simn_g[i];

    for (int i = tid * 4; i < 64 * PROJ_DIM; i += 256 * 4) {
        int r = i >> 8, c = i & 255;
        float4 v = *(const float4*)&h_g[(size_t)(row0 + r) * PROJ_DIM + c];
        float* d = &h_s[r * HS + c];
        d[0] = v.x; d[1] = v.y; d[2] = v.z; d[3] = v.w;
    }
    __syncthreads();

    const int row = tid >> 2;
    const int q = tid & 3;

    float ss = 0.f;
    const float* hrow = &h_s[row * HS];
    for (int p = q * 64; p < q * 64 + 64; p++) {
        float v = hrow[p];
        ss += v * v;
    }
    ss += __shfl_xor_sync(0xffffffffu, ss, 1);
    ss += __shfl_xor_sync(0xffffffffu, ss, 2);
    const float scal = scale_g / fmaxf(sqrtf(ss), 1e-12f);

    float acc[16];
#pragma unroll
    for (int j = 0; j < 16; j++) acc[j] = 0.f;
#pragma unroll 4
    for (int p = 0; p < PROJ_DIM; p++) {
        float hv = hrow[p];
        const float* sp = &simn_s[p * NEXP + q * 16];
#pragma unroll
        for (int j = 0; j < 16; j += 4) {
            float4 s4 = *(const float4*)&sp[j];
            acc[j + 0] += hv * s4.x;
            acc[j + 1] += hv * s4.y;
            acc[j + 2] += hv * s4.z;
            acc[j + 3] += hv * s4.w;
        }
    }

    float lg[16];
    float mymax = -3.4e38f;
#pragma unroll
    for (int j = 0; j < 16; j++) {
        int e = q * 16 + j;
        float l = acc[j] * scal;
        if (mask[e] == 0.f) l = NEG_INF;
        lg[j] = l;
        mymax = fmaxf(mymax, l);
    }
    {
        float* obase = out + (size_t)(row0 + row) * NEXP + q * 16;
#pragma unroll
        for (int j = 0; j < 16; j += 4) {
            float4 v; v.x = lg[j]; v.y = lg[j + 1]; v.z = lg[j + 2]; v.w = lg[j + 3];
            *(float4*)(obase + j) = v;
        }
    }
    mymax = fmaxf(mymax, __shfl_xor_sync(0xffffffffu, mymax, 1));
    mymax = fmaxf(mymax, __shfl_xor_sync(0xffffffffu, mymax, 2));

    float ex[16];
    float sum = 0.f;
#pragma unroll
    for (int j = 0; j < 16; j++) {
        ex[j] = expf(lg[j] - mymax);
        sum += ex[j];
    }
    sum += __shfl_xor_sync(0xffffffffu, sum, 1);
    sum += __shfl_xor_sync(0xffffffffu, sum, 2);
    const float inv = 1.f / sum;

    float scs[16];
#pragma unroll
    for (int j = 0; j < 16; j++) {
        scs[j] = ex[j] * inv + 1e-14f;
        sc_s[row * SC + q * 16 + j] = scs[j];
    }
    __syncthreads();

    int cnt = 0;
    const float* srow = &sc_s[row * SC];
#pragma unroll
    for (int j = 0; j < 16; j++) {
        const float v = scs[j];
        const int gi = q * 16 + j;
        float prefix = 0.f;
#pragma unroll 8
        for (int u = 0; u < NEXP; u++) {
            float su = srow[u];
            if (su > v || (su == v && u < gi)) prefix += su;
        }
        cnt += (prefix < 1.0f) ? 1 : 0;
    }
    cnt += __shfl_xor_sync(0xffffffffu, cnt, 1);
    cnt += __shfl_xor_sync(0xffffffffu, cnt, 2);

    if (q == 0 && (size_t)out_size >= (size_t)M * NEXP + (size_t)M) {
        int a = (int)activecnt_g;
        if (cnt > a) cnt = a;
        out[(size_t)M * NEXP + row0 + row] = (float)cnt;
    }
}

// ---------------------------------------------------------------------------
extern "C" void kernel_launch(void* const* d_in, const int* in_sizes, int n_in,
                              void* d_out, int out_size) {
    const float* x    = (const float*)d_in[0];
    const float* W    = (const float*)d_in[1];
    const float* b    = (const float*)d_in[2];
    const float* sim  = (const float*)d_in[3];
    const float* temp = (const float*)d_in[4];
    const float* mask = (const float*)d_in[5];
    float* out = (float*)d_out;

    const int M = in_sizes[0] / MODEL_DIM;   // 16384

    prep_kernel<<<1, 256>>>(sim, temp, mask);
    wconv_kernel<<<(PROJ_DIM * MODEL_DIM / 4) / 256, 256>>>(W);

    cudaFuncSetAttribute(gemm_mma_kernel, cudaFuncAttributeMaxDynamicSharedMemorySize,
                         GEMM_SMEM);
    gemm_mma_kernel<<<M / BM, 512, GEMM_SMEM>>>(x, b);

    cudaFuncSetAttribute(gate_kernel, cudaFuncAttributeMaxDynamicSharedMemorySize,
                         GATE_SMEM);
    gate_kernel<<<M / 64, 256, GATE_SMEM>>>(mask, out, M, out_size);
}